// round 12
// baseline (speedup 1.0000x reference)
#include <cuda_runtime.h>
#include <cuda_fp16.h>
#include <cstdint>
#include <math.h>

#define MROWS  8192
#define KD     2048
#define NCOLS  6144
#define DOUT   2048
#define Tn     4096
#define NSTAGE 32            // KD / 64
#define ROWB   144           // smem row stride: 128B data (k64 fp16) + 16B pad
#define TILEB  (128*ROWB)    // 18432 bytes per tile
#define STAGE_BYTES (3*TILEB) // Ah, Al, Bh = 55296
#define NPIPE  2
#define SMEM_TOTAL (NPIPE*STAGE_BYTES)   // 110592 >= epilogue tile 128*132*4 = 67584

// ---------------- static scratch ----------------
__device__ __align__(1024) __half g_Ah[(size_t)MROWS * KD];
__device__ __align__(1024) __half g_Al[(size_t)MROWS * KD];
__device__ __align__(1024) __half g_Bh[(size_t)NCOLS * KD];
__device__ float g_posv[Tn];

// ---------------- PTX helpers ----------------
__device__ __forceinline__ uint32_t smem_u32(const void* p) {
    uint32_t a;
    asm("{ .reg .u64 t; cvta.to.shared.u64 t, %1; cvt.u32.u64 %0, t; }" : "=r"(a) : "l"(p));
    return a;
}
__device__ __forceinline__ void cp16(uint32_t s, const void* g) {
    asm volatile("cp.async.cg.shared.global [%0], [%1], 16;" :: "r"(s), "l"(g) : "memory");
}
#define CP_COMMIT() asm volatile("cp.async.commit_group;" ::: "memory")
#define CP_WAIT1()  asm volatile("cp.async.wait_group 1;" ::: "memory")
#define CP_WAIT0()  asm volatile("cp.async.wait_group 0;" ::: "memory")

__device__ __forceinline__ void ldsm4(uint32_t* r, uint32_t addr) {
    asm volatile("ldmatrix.sync.aligned.m8n8.x4.shared.b16 {%0,%1,%2,%3}, [%4];"
                 : "=r"(r[0]), "=r"(r[1]), "=r"(r[2]), "=r"(r[3]) : "r"(addr));
}
__device__ __forceinline__ void hmma(float* c, const uint32_t* a, const uint32_t* b) {
    asm volatile("mma.sync.aligned.m16n8k16.row.col.f32.f16.f16.f32 "
                 "{%0,%1,%2,%3}, {%4,%5,%6,%7}, {%8,%9}, {%0,%1,%2,%3};"
                 : "+f"(c[0]), "+f"(c[1]), "+f"(c[2]), "+f"(c[3])
                 : "r"(a[0]), "r"(a[1]), "r"(a[2]), "r"(a[3]), "r"(b[0]), "r"(b[1]));
}

// ---------------- convert kernels ----------------
__device__ __forceinline__ void split_h(float v, __half& h, __half& l) {
    h = __float2half_rn(v);
    l = __float2half_rn(v - __half2float(h));
}

__global__ void conv_a(const float* __restrict__ x) {
    size_t base = ((size_t)blockIdx.x * blockDim.x + threadIdx.x) * 4;
    float4 v = *(const float4*)(x + base);
    __half h[4], l[4];
    split_h(v.x, h[0], l[0]); split_h(v.y, h[1], l[1]);
    split_h(v.z, h[2], l[2]); split_h(v.w, h[3], l[3]);
    #pragma unroll
    for (int i = 0; i < 4; i++) { g_Ah[base + i] = h[i]; g_Al[base + i] = l[i]; }
}

__global__ void conv_b(const float* __restrict__ W) {
    __shared__ float t[32][33];
    int n0 = blockIdx.x * 32, k0 = blockIdx.y * 32;
    int tx = threadIdx.x, ty = threadIdx.y;    // 32 x 8
    #pragma unroll
    for (int i = 0; i < 4; i++)
        t[ty + 8 * i][tx] = W[(size_t)(k0 + ty + 8 * i) * NCOLS + n0 + tx];
    __syncthreads();
    #pragma unroll
    for (int i = 0; i < 4; i++) {
        int n = n0 + ty + 8 * i;
        int k = k0 + tx;
        g_Bh[(size_t)n * KD + k] = __float2half_rn(t[tx][ty + 8 * i]);
    }
}

__global__ void copy_pos(const float* __restrict__ pos) {
    int i = blockIdx.x * blockDim.x + threadIdx.x;
    if (i < Tn) g_posv[i] = pos[i];
}

// ---------------- main GEMM + fused epilogue ----------------
__global__ __launch_bounds__(128, 2)
void gemm_k(const float* __restrict__ gq, const float* __restrict__ gk,
            float* __restrict__ out) {
    extern __shared__ char smem[];
    const uint32_t TILES = smem_u32(smem);
    const int tid = threadIdx.x, wid = tid >> 5, lane = tid & 31;
    const int row0 = blockIdx.y << 7;
    const int col0 = blockIdx.x << 7;

    // warp grid 2(M) x 2(N), warp tile 64x64
    const int wm = wid >> 1, wn = wid & 1;

    // producer: thread owns row `tid` of each of the 3 tiles (128B per tile per stage)
    const __half* pAh = g_Ah + (size_t)(row0 + tid) * KD;
    const __half* pAl = g_Al + (size_t)(row0 + tid) * KD;
    const __half* pBh = g_Bh + (size_t)(col0 + tid) * KD;
    const uint32_t srow = (uint32_t)(tid * ROWB);

    // ldmatrix per-lane offsets within a tile (k16 sub-chunk kk adds kk*32 bytes)
    const uint32_t aLane = (uint32_t)((wm * 64 + (lane & 7) + ((lane >> 3) & 1) * 8) * ROWB
                                      + (lane >> 4) * 16);
    const uint32_t bLane = (uint32_t)((wn * 64 + (lane & 7) + (lane >> 4) * 8) * ROWB
                                      + ((lane >> 3) & 1) * 16);

    float acc[4][8][4];
    #pragma unroll
    for (int m = 0; m < 4; m++)
        #pragma unroll
        for (int n = 0; n < 8; n++)
            #pragma unroll
            for (int r = 0; r < 4; r++)
                acc[m][n][r] = 0.0f;

    // -------- prologue: prefetch stage 0 --------
    {
        const uint32_t d = TILES + srow;
        const char* a = (const char*)pAh;
        const char* l = (const char*)pAl;
        const char* b = (const char*)pBh;
        #pragma unroll
        for (int o = 0; o < 128; o += 16) {
            cp16(d + 0*TILEB + o, a + o);
            cp16(d + 1*TILEB + o, l + o);
            cp16(d + 2*TILEB + o, b + o);
        }
        CP_COMMIT();
    }

    // -------- mainloop --------
    for (int f = 0; f < NSTAGE; f++) {
        // issue stage f+1 (group committed unconditionally so WAIT1 is safe)
        if (f + 1 < NSTAGE) {
            const uint32_t d = TILES + ((f + 1) & 1) * STAGE_BYTES + srow;
            const char* a = (const char*)(pAh + (size_t)(f + 1) * 64);
            const char* l = (const char*)(pAl + (size_t)(f + 1) * 64);
            const char* b = (const char*)(pBh + (size_t)(f + 1) * 64);
            #pragma unroll
            for (int o = 0; o < 128; o += 16) {
                cp16(d + 0*TILEB + o, a + o);
                cp16(d + 1*TILEB + o, l + o);
                cp16(d + 2*TILEB + o, b + o);
            }
        }
        CP_COMMIT();
        CP_WAIT1();          // stage f resident
        __syncthreads();

        const uint32_t sb = TILES + (f & 1) * STAGE_BYTES;
        #pragma unroll
        for (int kk = 0; kk < 4; kk++) {
            uint32_t ah[4][4], al_[4][4], bh[4][4];
            #pragma unroll
            for (int mt = 0; mt < 4; mt++)
                ldsm4(ah[mt],  sb + 0*TILEB + aLane + kk * 32 + mt * 16 * ROWB);
            #pragma unroll
            for (int nt2 = 0; nt2 < 4; nt2++)
                ldsm4(bh[nt2], sb + 2*TILEB + bLane + kk * 32 + nt2 * 16 * ROWB);
            #pragma unroll
            for (int mt = 0; mt < 4; mt++)
                ldsm4(al_[mt], sb + 1*TILEB + aLane + kk * 32 + mt * 16 * ROWB);

            #pragma unroll
            for (int mt = 0; mt < 4; mt++)
                #pragma unroll
                for (int nt = 0; nt < 8; nt++)
                    hmma(acc[mt][nt], ah[mt], &bh[nt >> 1][(nt & 1) * 2]);
            #pragma unroll
            for (int mt = 0; mt < 4; mt++)
                #pragma unroll
                for (int nt = 0; nt < 8; nt++)
                    hmma(acc[mt][nt], al_[mt], &bh[nt >> 1][(nt & 1) * 2]);
        }
        __syncthreads();     // protect stage f buffer before producer overwrites (NPIPE=2)
    }
    CP_WAIT0();
    __syncthreads();

    // -------- write accumulators to smem fp32 tile (128x132) --------
    float* tile = (float*)smem;
    #pragma unroll
    for (int mt = 0; mt < 4; mt++) {
        const int r = wm * 64 + mt * 16 + (lane >> 2);
        #pragma unroll
        for (int nt = 0; nt < 8; nt++) {
            const int c = wn * 64 + nt * 8 + 2 * (lane & 3);
            *(float2*)(tile + r * 132 + c)       = make_float2(acc[mt][nt][0], acc[mt][nt][1]);
            *(float2*)(tile + (r + 8) * 132 + c) = make_float2(acc[mt][nt][2], acc[mt][nt][3]);
        }
    }
    __syncthreads();

    // -------- fused RMSNorm + RoPE epilogue (128 threads: 16 rows each) --------
    const int tx = tid & 15;
    const int ty = tid >> 4;                 // 0..7
    const int region = col0 >> 11;           // 0=q, 1=k, 2=v
    const int colr0  = col0 & 2047;
    float* const outbase = out + (size_t)region * ((size_t)MROWS * DOUT);

    if (region == 2) {
        #pragma unroll
        for (int i = 0; i < 16; i++) {
            const int rr = ty * 16 + i;
            const float* s = tile + rr * 132 + tx * 8;
            float* p = outbase + (size_t)(row0 + rr) * DOUT + colr0 + tx * 8;
            *(float4*)(p + 0) = make_float4(s[0], s[1], s[2], s[3]);
            *(float4*)(p + 4) = make_float4(s[4], s[5], s[6], s[7]);
        }
        return;
    }

    const float* const g = (region == 0) ? gq : gk;
    float gv[8];
    #pragma unroll
    for (int j = 0; j < 8; j++) gv[j] = __ldg(g + tx * 8 + j);

    const float NLOG = -13.287712379549449f / 64.0f;   // -log2(10000)/64
    #pragma unroll
    for (int i = 0; i < 16; i++) {
        const int rr = ty * 16 + i;
        const int r  = row0 + rr;
        float v[8];
        const float* s = tile + rr * 132 + tx * 8;
        #pragma unroll
        for (int j = 0; j < 8; j++) v[j] = s[j];

        float ss = 0.0f;
        #pragma unroll
        for (int j = 0; j < 8; j++) ss += v[j] * v[j];
        ss += __shfl_xor_sync(0xffffffffu, ss, 1);
        ss += __shfl_xor_sync(0xffffffffu, ss, 2);
        ss += __shfl_xor_sync(0xffffffffu, ss, 4);
        ss += __shfl_xor_sync(0xffffffffu, ss, 8);
        const float rinv = rsqrtf(ss * (1.0f / 128.0f) + 1e-6f);
        const float pv = g_posv[r & (Tn - 1)];

        float o[8];
        #pragma unroll
        for (int j = 0; j < 8; j++) {
            const float val = v[j] * rinv * gv[j];
            const int   c   = tx * 8 + j;
            const float invf = exp2f((float)(c & 63) * NLOG);
            float sn, cs;
            sincosf(pv * invf, &sn, &cs);
            const float other = __shfl_xor_sync(0xffffffffu, val, 8);
            o[j] = (tx < 8) ? (val * cs - other * sn) : (other * sn + val * cs);
        }
        float* q = outbase + (size_t)r * DOUT + colr0 + tx * 8;
        *(float4*)(q + 0) = make_float4(o[0], o[1], o[2], o[3]);
        *(float4*)(q + 4) = make_float4(o[4], o[5], o[6], o[7]);
    }
}

extern "C" void kernel_launch(void* const* d_in, const int* in_sizes, int n_in,
                              void* d_out, int out_size) {
    const float* x   = (const float*)d_in[0];
    const float* W   = (const float*)d_in[1];
    const float* gq  = (const float*)d_in[2];
    const float* gk  = (const float*)d_in[3];
    const float* pos = (const float*)d_in[4];
    float* out = (float*)d_out;

    cudaFuncSetAttribute(gemm_k, cudaFuncAttributeMaxDynamicSharedMemorySize, SMEM_TOTAL);

    conv_a<<<(MROWS * KD / 4) / 256, 256>>>(x);
    conv_b<<<dim3(NCOLS / 32, KD / 32), dim3(32, 8)>>>(W);
    copy_pos<<<Tn / 256, 256>>>(pos);

    dim3 grid(NCOLS / 128, MROWS / 128);   // (48, 64)
    gemm_k<<<grid, 128, SMEM_TOTAL>>>(gq, gk, out);
}

// round 14
// speedup vs baseline: 1.5380x; 1.5380x over previous
#include <cuda_runtime.h>
#include <cuda_fp16.h>
#include <cstdint>
#include <math.h>

#define MROWS  8192
#define KD     2048
#define NCOLS  6144
#define DOUT   2048
#define Tn     4096
#define NSTAGE 64            // KD / 32
#define ROWB   80            // smem row stride: 64B data (k32 fp16) + 16B pad
#define TILEB  (128*ROWB)    // 10240 bytes per tile
#define STAGE_BYTES (3*TILEB) // Ah, Al, Bh = 30720
#define NPIPE  3
#define SMEM_TOTAL (NPIPE*STAGE_BYTES)   // 92160 >= epilogue tile 128*132*4 = 67584

// ---------------- static scratch ----------------
__device__ __align__(1024) __half g_Ah[(size_t)MROWS * KD];
__device__ __align__(1024) __half g_Al[(size_t)MROWS * KD];
__device__ __align__(1024) __half g_Bh[(size_t)NCOLS * KD];
__device__ float g_posv[Tn];

// ---------------- PTX helpers ----------------
__device__ __forceinline__ uint32_t smem_u32(const void* p) {
    uint32_t a;
    asm("{ .reg .u64 t; cvta.to.shared.u64 t, %1; cvt.u32.u64 %0, t; }" : "=r"(a) : "l"(p));
    return a;
}
__device__ __forceinline__ void cp16(uint32_t s, const void* g) {
    asm volatile("cp.async.cg.shared.global [%0], [%1], 16;" :: "r"(s), "l"(g) : "memory");
}
#define CP_COMMIT() asm volatile("cp.async.commit_group;" ::: "memory")
#define CP_WAIT1()  asm volatile("cp.async.wait_group 1;" ::: "memory")
#define CP_WAIT0()  asm volatile("cp.async.wait_group 0;" ::: "memory")

__device__ __forceinline__ void ldsm4(uint32_t* r, uint32_t addr) {
    asm volatile("ldmatrix.sync.aligned.m8n8.x4.shared.b16 {%0,%1,%2,%3}, [%4];"
                 : "=r"(r[0]), "=r"(r[1]), "=r"(r[2]), "=r"(r[3]) : "r"(addr));
}
__device__ __forceinline__ void hmma(float* c, const uint32_t* a, const uint32_t* b) {
    asm volatile("mma.sync.aligned.m16n8k16.row.col.f32.f16.f16.f32 "
                 "{%0,%1,%2,%3}, {%4,%5,%6,%7}, {%8,%9}, {%0,%1,%2,%3};"
                 : "+f"(c[0]), "+f"(c[1]), "+f"(c[2]), "+f"(c[3])
                 : "r"(a[0]), "r"(a[1]), "r"(a[2]), "r"(a[3]), "r"(b[0]), "r"(b[1]));
}

// ---------------- convert kernels ----------------
__device__ __forceinline__ void split_h(float v, __half& h, __half& l) {
    h = __float2half_rn(v);
    l = __float2half_rn(v - __half2float(h));
}

__global__ void conv_a(const float* __restrict__ x) {
    size_t base = ((size_t)blockIdx.x * blockDim.x + threadIdx.x) * 4;
    float4 v = *(const float4*)(x + base);
    __half h[4], l[4];
    split_h(v.x, h[0], l[0]); split_h(v.y, h[1], l[1]);
    split_h(v.z, h[2], l[2]); split_h(v.w, h[3], l[3]);
    #pragma unroll
    for (int i = 0; i < 4; i++) { g_Ah[base + i] = h[i]; g_Al[base + i] = l[i]; }
}

__global__ void conv_b(const float* __restrict__ W) {
    __shared__ float t[32][33];
    int n0 = blockIdx.x * 32, k0 = blockIdx.y * 32;
    int tx = threadIdx.x, ty = threadIdx.y;    // 32 x 8
    #pragma unroll
    for (int i = 0; i < 4; i++)
        t[ty + 8 * i][tx] = W[(size_t)(k0 + ty + 8 * i) * NCOLS + n0 + tx];
    __syncthreads();
    #pragma unroll
    for (int i = 0; i < 4; i++) {
        int n = n0 + ty + 8 * i;
        int k = k0 + tx;
        g_Bh[(size_t)n * KD + k] = __float2half_rn(t[tx][ty + 8 * i]);
    }
}

__global__ void copy_pos(const float* __restrict__ pos) {
    int i = blockIdx.x * blockDim.x + threadIdx.x;
    if (i < Tn) g_posv[i] = pos[i];
}

// ---------------- main GEMM + fused epilogue ----------------
__global__ __launch_bounds__(256, 2)
void gemm_k(const float* __restrict__ gq, const float* __restrict__ gk,
            float* __restrict__ out) {
    extern __shared__ char smem[];
    const uint32_t TILES = smem_u32(smem);
    const int tid = threadIdx.x, wid = tid >> 5, lane = tid & 31;
    const int row0 = blockIdx.y << 7;
    const int col0 = blockIdx.x << 7;

    // warp grid 4(M) x 2(N), warp tile 32x64
    const int wm = wid >> 1, wn = wid & 1;

    // producer: 256 threads; thread owns half (32B) of row prow in each of 3 tiles
    const int prow = tid >> 1, phalf = tid & 1;
    const __half* pAh = g_Ah + (size_t)(row0 + prow) * KD + phalf * 16;
    const __half* pAl = g_Al + (size_t)(row0 + prow) * KD + phalf * 16;
    const __half* pBh = g_Bh + (size_t)(col0 + prow) * KD + phalf * 16;
    const uint32_t srow = (uint32_t)(prow * ROWB + phalf * 32);

    // ldmatrix per-lane offsets within a tile (k16 sub-chunk kk adds kk*32 bytes)
    const uint32_t aLane = (uint32_t)((wm * 32 + (lane & 7) + ((lane >> 3) & 1) * 8) * ROWB
                                      + (lane >> 4) * 16);
    const uint32_t bLane = (uint32_t)((wn * 64 + (lane & 7) + (lane >> 4) * 8) * ROWB
                                      + ((lane >> 3) & 1) * 16);

    float acc[2][8][4];
    #pragma unroll
    for (int m = 0; m < 2; m++)
        #pragma unroll
        for (int n = 0; n < 8; n++)
            #pragma unroll
            for (int r = 0; r < 4; r++)
                acc[m][n][r] = 0.0f;

    // -------- prologue: prefetch NPIPE-1 stages --------
    #pragma unroll
    for (int f = 0; f < NPIPE - 1; f++) {
        const uint32_t d = TILES + f * STAGE_BYTES + srow;
        const char* a = (const char*)(pAh + (size_t)f * 32);
        const char* l = (const char*)(pAl + (size_t)f * 32);
        const char* b = (const char*)(pBh + (size_t)f * 32);
        cp16(d + 0*TILEB, a); cp16(d + 0*TILEB + 16, a + 16);
        cp16(d + 1*TILEB, l); cp16(d + 1*TILEB + 16, l + 16);
        cp16(d + 2*TILEB, b); cp16(d + 2*TILEB + 16, b + 16);
        CP_COMMIT();
    }

    // -------- mainloop (R9 structure) --------
    for (int f = 0; f < NSTAGE; f++) {
        CP_WAIT1();
        __syncthreads();

        if (f + NPIPE - 1 < NSTAGE) {
            const uint32_t d = TILES + ((f + NPIPE - 1) % NPIPE) * STAGE_BYTES + srow;
            const char* a = (const char*)(pAh + (size_t)(f + NPIPE - 1) * 32);
            const char* l = (const char*)(pAl + (size_t)(f + NPIPE - 1) * 32);
            const char* b = (const char*)(pBh + (size_t)(f + NPIPE - 1) * 32);
            cp16(d + 0*TILEB, a); cp16(d + 0*TILEB + 16, a + 16);
            cp16(d + 1*TILEB, l); cp16(d + 1*TILEB + 16, l + 16);
            cp16(d + 2*TILEB, b); cp16(d + 2*TILEB + 16, b + 16);
        }
        CP_COMMIT();

        const uint32_t sb = TILES + (f % NPIPE) * STAGE_BYTES;
        #pragma unroll
        for (int kk = 0; kk < 2; kk++) {
            uint32_t ah[2][4], al_[2][4], bh[4][4];
            #pragma unroll
            for (int mt = 0; mt < 2; mt++)
                ldsm4(ah[mt],  sb + 0*TILEB + aLane + kk * 32 + mt * 16 * ROWB);
            #pragma unroll
            for (int nt2 = 0; nt2 < 4; nt2++)
                ldsm4(bh[nt2], sb + 2*TILEB + bLane + kk * 32 + nt2 * 16 * ROWB);
            #pragma unroll
            for (int mt = 0; mt < 2; mt++)
                ldsm4(al_[mt], sb + 1*TILEB + aLane + kk * 32 + mt * 16 * ROWB);

            #pragma unroll
            for (int mt = 0; mt < 2; mt++)
                #pragma unroll
                for (int nt = 0; nt < 8; nt++)
                    hmma(acc[mt][nt], ah[mt], &bh[nt >> 1][(nt & 1) * 2]);
            #pragma unroll
            for (int mt = 0; mt < 2; mt++)
                #pragma unroll
                for (int nt = 0; nt < 8; nt++)
                    hmma(acc[mt][nt], al_[mt], &bh[nt >> 1][(nt & 1) * 2]);
        }
    }
    CP_WAIT0();
    __syncthreads();

    // -------- write accumulators to smem fp32 tile (128x132) --------
    float* tile = (float*)smem;
    #pragma unroll
    for (int mt = 0; mt < 2; mt++) {
        const int r = wm * 32 + mt * 16 + (lane >> 2);
        #pragma unroll
        for (int nt = 0; nt < 8; nt++) {
            const int c = wn * 64 + nt * 8 + 2 * (lane & 3);
            *(float2*)(tile + r * 132 + c)       = make_float2(acc[mt][nt][0], acc[mt][nt][1]);
            *(float2*)(tile + (r + 8) * 132 + c) = make_float2(acc[mt][nt][2], acc[mt][nt][3]);
        }
    }
    __syncthreads();

    // -------- fused RMSNorm + RoPE epilogue (256 threads: 8 rows each) --------
    const int tx = tid & 15;
    const int ty = tid >> 4;                 // 0..15
    const int region = col0 >> 11;           // 0=q, 1=k, 2=v
    const int colr0  = col0 & 2047;
    float* const outbase = out + (size_t)region * ((size_t)MROWS * DOUT);

    if (region == 2) {
        #pragma unroll
        for (int i = 0; i < 8; i++) {
            const int rr = ty * 8 + i;
            const float* s = tile + rr * 132 + tx * 8;
            float* p = outbase + (size_t)(row0 + rr) * DOUT + colr0 + tx * 8;
            *(float4*)(p + 0) = make_float4(s[0], s[1], s[2], s[3]);
            *(float4*)(p + 4) = make_float4(s[4], s[5], s[6], s[7]);
        }
        return;
    }

    const float* const g = (region == 0) ? gq : gk;
    float gv[8];
    #pragma unroll
    for (int j = 0; j < 8; j++) gv[j] = __ldg(g + tx * 8 + j);

    const float NLOG = -13.287712379549449f / 64.0f;   // -log2(10000)/64
    #pragma unroll
    for (int i = 0; i < 8; i++) {
        const int rr = ty * 8 + i;
        const int r  = row0 + rr;
        float v[8];
        const float* s = tile + rr * 132 + tx * 8;
        #pragma unroll
        for (int j = 0; j < 8; j++) v[j] = s[j];

        float ss = 0.0f;
        #pragma unroll
        for (int j = 0; j < 8; j++) ss += v[j] * v[j];
        ss += __shfl_xor_sync(0xffffffffu, ss, 1);
        ss += __shfl_xor_sync(0xffffffffu, ss, 2);
        ss += __shfl_xor_sync(0xffffffffu, ss, 4);
        ss += __shfl_xor_sync(0xffffffffu, ss, 8);
        const float rinv = rsqrtf(ss * (1.0f / 128.0f) + 1e-6f);
        const float pv = g_posv[r & (Tn - 1)];

        float o[8];
        #pragma unroll
        for (int j = 0; j < 8; j++) {
            const float val = v[j] * rinv * gv[j];
            const int   c   = tx * 8 + j;
            const float invf = exp2f((float)(c & 63) * NLOG);
            float sn, cs;
            sincosf(pv * invf, &sn, &cs);
            const float other = __shfl_xor_sync(0xffffffffu, val, 8);
            o[j] = (tx < 8) ? (val * cs - other * sn) : (other * sn + val * cs);
        }
        float* q = outbase + (size_t)r * DOUT + colr0 + tx * 8;
        *(float4*)(q + 0) = make_float4(o[0], o[1], o[2], o[3]);
        *(float4*)(q + 4) = make_float4(o[4], o[5], o[6], o[7]);
    }
}

extern "C" void kernel_launch(void* const* d_in, const int* in_sizes, int n_in,
                              void* d_out, int out_size) {
    const float* x   = (const float*)d_in[0];
    const float* W   = (const float*)d_in[1];
    const float* gq  = (const float*)d_in[2];
    const float* gk  = (const float*)d_in[3];
    const float* pos = (const float*)d_in[4];
    float* out = (float*)d_out;

    cudaFuncSetAttribute(gemm_k, cudaFuncAttributeMaxDynamicSharedMemorySize, SMEM_TOTAL);

    conv_a<<<(MROWS * KD / 4) / 256, 256>>>(x);
    conv_b<<<dim3(NCOLS / 32, KD / 32), dim3(32, 8)>>>(W);
    copy_pos<<<Tn / 256, 256>>>(pos);

    dim3 grid(NCOLS / 128, MROWS / 128);   // (48, 64)
    gemm_k<<<grid, 256, SMEM_TOTAL>>>(gq, gk, out);
}

// round 15
// speedup vs baseline: 2.4958x; 1.6227x over previous
#include <cuda_runtime.h>
#include <cuda_fp16.h>
#include <cstdint>
#include <math.h>

#define MROWS  8192
#define KD     2048
#define NCOLS  6144
#define DOUT   2048
#define Tn     4096
#define NSTAGE 64            // KD / 32
#define ROWB   80            // smem row stride: 64B data (k32 fp16) + 16B pad
#define TILEB  (128*ROWB)    // 10240 bytes per tile
#define STAGE_BYTES (2*TILEB) // Ah, Bh = 20480
#define NPIPE  4
#define SMEM_TOTAL (NPIPE*STAGE_BYTES)   // 81920 >= epilogue tile 128*132*4 = 67584

// ---------------- static scratch ----------------
__device__ __align__(1024) __half g_Ah[(size_t)MROWS * KD];
__device__ __align__(1024) __half g_Bh[(size_t)NCOLS * KD];
__device__ float g_posv[Tn];

// ---------------- PTX helpers ----------------
__device__ __forceinline__ uint32_t smem_u32(const void* p) {
    uint32_t a;
    asm("{ .reg .u64 t; cvta.to.shared.u64 t, %1; cvt.u32.u64 %0, t; }" : "=r"(a) : "l"(p));
    return a;
}
__device__ __forceinline__ void cp16(uint32_t s, const void* g) {
    asm volatile("cp.async.cg.shared.global [%0], [%1], 16;" :: "r"(s), "l"(g) : "memory");
}
#define CP_COMMIT() asm volatile("cp.async.commit_group;" ::: "memory")
#define CP_WAIT2()  asm volatile("cp.async.wait_group 2;" ::: "memory")
#define CP_WAIT0()  asm volatile("cp.async.wait_group 0;" ::: "memory")

__device__ __forceinline__ void ldsm4(uint32_t* r, uint32_t addr) {
    asm volatile("ldmatrix.sync.aligned.m8n8.x4.shared.b16 {%0,%1,%2,%3}, [%4];"
                 : "=r"(r[0]), "=r"(r[1]), "=r"(r[2]), "=r"(r[3]) : "r"(addr));
}
__device__ __forceinline__ void hmma(float* c, const uint32_t* a, const uint32_t* b) {
    asm volatile("mma.sync.aligned.m16n8k16.row.col.f32.f16.f16.f32 "
                 "{%0,%1,%2,%3}, {%4,%5,%6,%7}, {%8,%9}, {%0,%1,%2,%3};"
                 : "+f"(c[0]), "+f"(c[1]), "+f"(c[2]), "+f"(c[3])
                 : "r"(a[0]), "r"(a[1]), "r"(a[2]), "r"(a[3]), "r"(b[0]), "r"(b[1]));
}

// ---------------- convert kernels ----------------
__global__ void conv_a(const float* __restrict__ x) {
    size_t base = ((size_t)blockIdx.x * blockDim.x + threadIdx.x) * 4;
    float4 v = *(const float4*)(x + base);
    __half2* dst = (__half2*)(g_Ah + base);
    dst[0] = __floats2half2_rn(v.x, v.y);
    dst[1] = __floats2half2_rn(v.z, v.w);
}

__global__ void conv_b(const float* __restrict__ W) {
    __shared__ float t[32][33];
    int n0 = blockIdx.x * 32, k0 = blockIdx.y * 32;
    int tx = threadIdx.x, ty = threadIdx.y;    // 32 x 8
    #pragma unroll
    for (int i = 0; i < 4; i++)
        t[ty + 8 * i][tx] = W[(size_t)(k0 + ty + 8 * i) * NCOLS + n0 + tx];
    __syncthreads();
    #pragma unroll
    for (int i = 0; i < 4; i++) {
        int n = n0 + ty + 8 * i;
        int k = k0 + tx;
        g_Bh[(size_t)n * KD + k] = __float2half_rn(t[tx][ty + 8 * i]);
    }
}

__global__ void copy_pos(const float* __restrict__ pos) {
    int i = blockIdx.x * blockDim.x + threadIdx.x;
    if (i < Tn) g_posv[i] = pos[i];
}

// ---------------- main GEMM + fused epilogue ----------------
__global__ __launch_bounds__(256, 2)
void gemm_k(const float* __restrict__ gq, const float* __restrict__ gk,
            float* __restrict__ out) {
    extern __shared__ char smem[];
    const uint32_t TILES = smem_u32(smem);
    const int tid = threadIdx.x, wid = tid >> 5, lane = tid & 31;
    const int row0 = blockIdx.y << 7;
    const int col0 = blockIdx.x << 7;

    // warp grid 4(M) x 2(N), warp tile 32x64
    const int wm = wid >> 1, wn = wid & 1;

    // producer: 256 threads; thread owns half (32B) of row prow in each of 2 tiles
    const int prow = tid >> 1, phalf = tid & 1;
    const __half* pAh = g_Ah + (size_t)(row0 + prow) * KD + phalf * 16;
    const __half* pBh = g_Bh + (size_t)(col0 + prow) * KD + phalf * 16;
    const uint32_t srow = (uint32_t)(prow * ROWB + phalf * 32);

    // ldmatrix per-lane offsets within a tile (k16 sub-chunk kk adds kk*32 bytes)
    const uint32_t aLane = (uint32_t)((wm * 32 + (lane & 7) + ((lane >> 3) & 1) * 8) * ROWB
                                      + (lane >> 4) * 16);
    const uint32_t bLane = (uint32_t)((wn * 64 + (lane & 7) + (lane >> 4) * 8) * ROWB
                                      + ((lane >> 3) & 1) * 16);

    float acc[2][8][4];
    #pragma unroll
    for (int m = 0; m < 2; m++)
        #pragma unroll
        for (int n = 0; n < 8; n++)
            #pragma unroll
            for (int r = 0; r < 4; r++)
                acc[m][n][r] = 0.0f;

    // -------- prologue: prefetch NPIPE-1 stages --------
    #pragma unroll
    for (int f = 0; f < NPIPE - 1; f++) {
        const uint32_t d = TILES + f * STAGE_BYTES + srow;
        const char* a = (const char*)(pAh + (size_t)f * 32);
        const char* b = (const char*)(pBh + (size_t)f * 32);
        cp16(d + 0*TILEB, a); cp16(d + 0*TILEB + 16, a + 16);
        cp16(d + 1*TILEB, b); cp16(d + 1*TILEB + 16, b + 16);
        CP_COMMIT();
    }

    // -------- mainloop --------
    for (int f = 0; f < NSTAGE; f++) {
        CP_WAIT2();
        __syncthreads();

        if (f + NPIPE - 1 < NSTAGE) {
            const uint32_t d = TILES + ((f + NPIPE - 1) & (NPIPE - 1)) * STAGE_BYTES + srow;
            const char* a = (const char*)(pAh + (size_t)(f + NPIPE - 1) * 32);
            const char* b = (const char*)(pBh + (size_t)(f + NPIPE - 1) * 32);
            cp16(d + 0*TILEB, a); cp16(d + 0*TILEB + 16, a + 16);
            cp16(d + 1*TILEB, b); cp16(d + 1*TILEB + 16, b + 16);
        }
        CP_COMMIT();

        const uint32_t sb = TILES + (f & (NPIPE - 1)) * STAGE_BYTES;
        #pragma unroll
        for (int kk = 0; kk < 2; kk++) {
            uint32_t ah[2][4], bh[4][4];
            #pragma unroll
            for (int mt = 0; mt < 2; mt++)
                ldsm4(ah[mt],  sb + 0*TILEB + aLane + kk * 32 + mt * 16 * ROWB);
            #pragma unroll
            for (int nt2 = 0; nt2 < 4; nt2++)
                ldsm4(bh[nt2], sb + 1*TILEB + bLane + kk * 32 + nt2 * 16 * ROWB);

            #pragma unroll
            for (int mt = 0; mt < 2; mt++)
                #pragma unroll
                for (int nt = 0; nt < 8; nt++)
                    hmma(acc[mt][nt], ah[mt], &bh[nt >> 1][(nt & 1) * 2]);
        }
    }
    CP_WAIT0();
    __syncthreads();

    // -------- write accumulators to smem fp32 tile (128x132) --------
    float* tile = (float*)smem;
    #pragma unroll
    for (int mt = 0; mt < 2; mt++) {
        const int r = wm * 32 + mt * 16 + (lane >> 2);
        #pragma unroll
        for (int nt = 0; nt < 8; nt++) {
            const int c = wn * 64 + nt * 8 + 2 * (lane & 3);
            *(float2*)(tile + r * 132 + c)       = make_float2(acc[mt][nt][0], acc[mt][nt][1]);
            *(float2*)(tile + (r + 8) * 132 + c) = make_float2(acc[mt][nt][2], acc[mt][nt][3]);
        }
    }
    __syncthreads();

    // -------- fused RMSNorm + RoPE epilogue (256 threads: 8 rows each) --------
    const int tx = tid & 15;
    const int ty = tid >> 4;                 // 0..15
    const int region = col0 >> 11;           // 0=q, 1=k, 2=v
    const int colr0  = col0 & 2047;
    float* const outbase = out + (size_t)region * ((size_t)MROWS * DOUT);

    if (region == 2) {
        #pragma unroll
        for (int i = 0; i < 8; i++) {
            const int rr = ty * 8 + i;
            const float* s = tile + rr * 132 + tx * 8;
            float* p = outbase + (size_t)(row0 + rr) * DOUT + colr0 + tx * 8;
            *(float4*)(p + 0) = make_float4(s[0], s[1], s[2], s[3]);
            *(float4*)(p + 4) = make_float4(s[4], s[5], s[6], s[7]);
        }
        return;
    }

    const float* const g = (region == 0) ? gq : gk;
    float gv[8];
    #pragma unroll
    for (int j = 0; j < 8; j++) gv[j] = __ldg(g + tx * 8 + j);

    const float NLOG = -13.287712379549449f / 64.0f;   // -log2(10000)/64
    #pragma unroll
    for (int i = 0; i < 8; i++) {
        const int rr = ty * 8 + i;
        const int r  = row0 + rr;
        float v[8];
        const float* s = tile + rr * 132 + tx * 8;
        #pragma unroll
        for (int j = 0; j < 8; j++) v[j] = s[j];

        float ss = 0.0f;
        #pragma unroll
        for (int j = 0; j < 8; j++) ss += v[j] * v[j];
        ss += __shfl_xor_sync(0xffffffffu, ss, 1);
        ss += __shfl_xor_sync(0xffffffffu, ss, 2);
        ss += __shfl_xor_sync(0xffffffffu, ss, 4);
        ss += __shfl_xor_sync(0xffffffffu, ss, 8);
        const float rinv = rsqrtf(ss * (1.0f / 128.0f) + 1e-6f);
        const float pv = g_posv[r & (Tn - 1)];

        float o[8];
        #pragma unroll
        for (int j = 0; j < 8; j++) {
            const float val = v[j] * rinv * gv[j];
            const int   c   = tx * 8 + j;
            const float invf = exp2f((float)(c & 63) * NLOG);
            float sn, cs;
            sincosf(pv * invf, &sn, &cs);
            const float other = __shfl_xor_sync(0xffffffffu, val, 8);
            o[j] = (tx < 8) ? (val * cs - other * sn) : (other * sn + val * cs);
        }
        float* q = outbase + (size_t)r * DOUT + colr0 + tx * 8;
        *(float4*)(q + 0) = make_float4(o[0], o[1], o[2], o[3]);
        *(float4*)(q + 4) = make_float4(o[4], o[5], o[6], o[7]);
    }
}

extern "C" void kernel_launch(void* const* d_in, const int* in_sizes, int n_in,
                              void* d_out, int out_size) {
    const float* x   = (const float*)d_in[0];
    const float* W   = (const float*)d_in[1];
    const float* gq  = (const float*)d_in[2];
    const float* gk  = (const float*)d_in[3];
    const float* pos = (const float*)d_in[4];
    float* out = (float*)d_out;

    cudaFuncSetAttribute(gemm_k, cudaFuncAttributeMaxDynamicSharedMemorySize, SMEM_TOTAL);

    conv_a<<<(MROWS * KD / 4) / 256, 256>>>(x);
    conv_b<<<dim3(NCOLS / 32, KD / 32), dim3(32, 8)>>>(W);
    copy_pos<<<Tn / 256, 256>>>(pos);

    dim3 grid(NCOLS / 128, MROWS / 128);   // (48, 64)
    gemm_k<<<grid, 256, SMEM_TOTAL>>>(gq, gk, out);
}